// round 9
// baseline (speedup 1.0000x reference)
#include <cuda_runtime.h>
#include <cstdint>

#define BNUM 4
#define HS 64
#define WS 64
#define HU 512
#define WU 512
#define CORI 90
#define CMNT 180
#define COFF 8
#define KCAND 1024
#define NCELL (HS*WS)       // 4096
#define NPIX (HU*WU)        // 262144

// output layout (concatenated flattened returns):
// minut [4,1024,4] | keep [4,1024] | enh_vis [4,512,512] | mask_up*255 | ori_field
#define MINUT_OFF 0
#define KEEP_OFF  16384
#define ENH_OFF   20480
#define MASK_OFF  1069056
#define ORI_OFF   2117632

// -------- device scratch --------
__device__ float g_mask[BNUM*NCELL];
__device__ float g_er[BNUM*NCELL];
__device__ float g_tA[BNUM*NPIX];
__device__ float g_tB[BNUM*NPIX];
__device__ float g_maskup[BNUM*NPIX];
__device__ unsigned g_emin[BNUM];
__device__ unsigned g_emax[BNUM];

__device__ __forceinline__ unsigned f2ord(float f){
    unsigned u=__float_as_uint(f);
    return (u & 0x80000000u) ? ~u : (u | 0x80000000u);
}
__device__ __forceinline__ float ord2f(unsigned u){
    u = (u & 0x80000000u) ? (u & 0x7fffffffu) : ~u;
    return __uint_as_float(u);
}

// -------- small 5x5 opening on [B,64,64] (+ minmax init) --------
__global__ void small_erode(const float* __restrict__ seg){
    int i=blockIdx.x*blockDim.x+threadIdx.x;
    if(i<BNUM){ g_emin[i]=0xFFFFFFFFu; g_emax[i]=0u; }
    if(i>=BNUM*NCELL) return;
    int b=i/NCELL, cell=i%NCELL, r=cell/WS, c=cell%WS;
    const float* s=seg+(size_t)b*NCELL;
    int y0=r-2<0?0:r-2, y1=r+2>HS-1?HS-1:r+2;
    int x0=c-2<0?0:c-2, x1=c+2>WS-1?WS-1:c+2;
    float m=1e30f;
    for(int y=y0;y<=y1;y++)
        for(int x=x0;x<=x1;x++)
            m=fminf(m, rintf(s[y*WS+x]));
    g_er[i]=m;
}
__global__ void small_dilate(){
    int i=blockIdx.x*blockDim.x+threadIdx.x;
    if(i>=BNUM*NCELL) return;
    int b=i/NCELL, cell=i%NCELL, r=cell/WS, c=cell%WS;
    const float* s=g_er+(size_t)b*NCELL;
    int y0=r-2<0?0:r-2, y1=r+2>HS-1?HS-1:r+2;
    int x0=c-2<0?0:c-2, x1=c+2>WS-1?WS-1:c+2;
    float m=-1e30f;
    for(int y=y0;y<=y1;y++)
        for(int x=x0;x<=x1;x++)
            m=fmaxf(m, s[y*WS+x]);
    g_mask[i]=m;
}

// ======== 40-wide separable opening, float4 (4 outputs/thread) ========
// window for output at p: [p-19, p+20], clamped (clamp == neutral fill).

// vertical: one thread = (y, x0..x0+3). 40 float4 row loads shared by 4 outputs.
template<bool MN, bool RND>
__global__ void __launch_bounds__(256) up_v4(const float* __restrict__ in, float* __restrict__ out){
    int i=blockIdx.x*256+threadIdx.x;
    if(i>=BNUM*NPIX/4) return;
    int b=i/(NPIX/4); int rem=i%(NPIX/4);
    int y=rem/(WU/4); int x0=(rem%(WU/4))*4;
    const float* base = in + (size_t)b*NPIX + x0;
    float m0=MN?1e30f:-1e30f, m1=m0, m2=m0, m3=m0;
    int a0=y-19; if(a0<0)a0=0;
    int a1=y+20; if(a1>HU-1)a1=HU-1;
    #pragma unroll 8
    for(int yy=a0;yy<=a1;yy++){
        float4 v=*reinterpret_cast<const float4*>(base+(size_t)yy*WU);
        if(RND){ v.x=rintf(v.x); v.y=rintf(v.y); v.z=rintf(v.z); v.w=rintf(v.w); }
        if(MN){ m0=fminf(m0,v.x); m1=fminf(m1,v.y); m2=fminf(m2,v.z); m3=fminf(m3,v.w); }
        else  { m0=fmaxf(m0,v.x); m1=fmaxf(m1,v.y); m2=fmaxf(m2,v.z); m3=fmaxf(m3,v.w); }
    }
    float4 o; o.x=m0; o.y=m1; o.z=m2; o.w=m3;
    *reinterpret_cast<float4*>(out + (size_t)b*NPIX + (size_t)y*WU + x0) = o;
}

// horizontal: one thread = (row, x0..x0+3). quads q=0..10 cover k=0..43
// (k = x - (x0-20)); output j needs k in [j+1, j+40]:
//   core = op(qm[1..9]);  j=3: op(core,qm[10]);  edges use e1..e3 (quad0), f0..f2 (quad10)
template<bool MN>
__global__ void __launch_bounds__(256) up_h4(const float* __restrict__ in, float* __restrict__ out){
    int i=blockIdx.x*256+threadIdx.x;
    if(i>=BNUM*NPIX/4) return;
    int b=i/(NPIX/4); int rem=i%(NPIX/4);
    int row=rem/(WU/4); int x0=(rem%(WU/4))*4;
    const float* rp = in + (size_t)b*NPIX + (size_t)row*WU;
    const float NEU=MN?1e30f:-1e30f;
    #define OPX(a,c) (MN?fminf(a,c):fmaxf(a,c))
    float qm[11];
    float e1,e2,e3,f0,f1,f2;
    #pragma unroll
    for(int q=0;q<11;q++){
        int bs=x0-20+4*q;
        float a0,a1,a2,a3;
        if(bs>=0 && bs+3<WU){
            float4 v=*reinterpret_cast<const float4*>(rp+bs);
            a0=v.x; a1=v.y; a2=v.z; a3=v.w;
        } else {
            a0=(bs  >=0 && bs  <WU)? rp[bs  ] : NEU;
            a1=(bs+1>=0 && bs+1<WU)? rp[bs+1] : NEU;
            a2=(bs+2>=0 && bs+2<WU)? rp[bs+2] : NEU;
            a3=(bs+3>=0 && bs+3<WU)? rp[bs+3] : NEU;
        }
        if(q==0){ e1=a1; e2=a2; e3=a3; }
        if(q==10){ f0=a0; f1=a1; f2=a2; }
        qm[q]=OPX(OPX(a0,a1),OPX(a2,a3));
    }
    float core=qm[1];
    #pragma unroll
    for(int k=2;k<=9;k++) core=OPX(core,qm[k]);
    float4 o;
    o.x=OPX(OPX(core,OPX(e1,e2)),OPX(e3,f0));
    o.y=OPX(OPX(core,OPX(e2,e3)),OPX(f0,f1));
    o.z=OPX(OPX(core,e3),OPX(f0,OPX(f1,f2)));
    o.w=OPX(core,qm[10]);
    *reinterpret_cast<float4*>(out + (size_t)b*NPIX + (size_t)row*WU + x0) = o;
    #undef OPX
}

// -------- enhanced min/max per batch --------
__global__ void enh_minmax(const float* __restrict__ enh){
    int b=blockIdx.y;
    const float* e=enh+(size_t)b*NPIX;
    const float* m=g_maskup+(size_t)b*NPIX;
    float mn=1e30f, mx=-1e30f;
    for(int p=blockIdx.x*blockDim.x+threadIdx.x; p<NPIX; p+=gridDim.x*blockDim.x){
        float v=e[p]*m[p];
        mn=fminf(mn,v); mx=fmaxf(mx,v);
    }
    for(int o=16;o;o>>=1){
        mn=fminf(mn,__shfl_down_sync(0xFFFFFFFFu,mn,o));
        mx=fmaxf(mx,__shfl_down_sync(0xFFFFFFFFu,mx,o));
    }
    __shared__ float smn[8], smx[8];
    int lane=threadIdx.x&31, w=threadIdx.x>>5;
    if(lane==0){ smn[w]=mn; smx[w]=mx; }
    __syncthreads();
    if(threadIdx.x==0){
        int nw=blockDim.x>>5;
        for(int i=1;i<nw;i++){ mn=fminf(mn,smn[i]); mx=fmaxf(mx,smx[i]); }
        atomicMin(&g_emin[b], f2ord(mn));
        atomicMax(&g_emax[b], f2ord(mx));
    }
}

// -------- detect (top-k + NMS), one block per batch --------
__global__ void __launch_bounds__(1024) detect_nms(
    const float* __restrict__ mscore, const float* __restrict__ mori,
    const float* __restrict__ mxo,    const float* __restrict__ myo,
    float* __restrict__ out)
{
    int b=blockIdx.x, tid=threadIdx.x;
    __shared__ unsigned long long keys[4096];   // 32KB
    __shared__ int s_nv;
    float* sx=(float*)(keys+1024);
    float* sy=(float*)(keys+1536);
    float* sa=(float*)(keys+2048);
    unsigned char* skeep=(unsigned char*)(keys+2560);

    const float* sc=mscore+(size_t)b*NCELL;
    const float* mk=g_mask +(size_t)b*NCELL;

    bool anyv=false;
    for(int t=tid;t<NCELL;t+=1024){
        float v=sc[t]*mk[t];
        bool val = v>0.5f;
        anyv |= val;
        float mv = val ? v : -1.0f;
        keys[t] = ((unsigned long long)(~f2ord(mv))<<32) | (unsigned)t;
    }
    if(__syncthreads_count(anyv)==0){
        float* om=out + MINUT_OFF + (size_t)b*KCAND*4 + (size_t)tid*4;
        om[0]=0.0f; om[1]=0.0f; om[2]=0.0f; om[3]=0.0f;
        out[KEEP_OFF + (size_t)b*KCAND + tid]=0.0f;
        return;
    }

    for(int k=2;k<=4096;k<<=1){
        for(int j=k>>1;j>0;j>>=1){
            for(int i=tid;i<4096;i+=1024){
                int ixj=i^j;
                if(ixj>i){
                    unsigned long long a=keys[i], c=keys[ixj];
                    bool up=((i&k)==0);
                    if((a>c)==up){ keys[i]=c; keys[ixj]=a; }
                }
            }
            __syncthreads();
        }
    }

    unsigned long long key=keys[tid];
    int idx=(int)(key & 0xFFFFFFFFull);
    float score=sc[idx]*mk[idx];
    bool valid = score>0.5f;
    float xc=0.0f, yc=0.0f, ang=0.0f;
    if(!valid) score=0.0f;
    if(valid){
        int r=idx>>6, c=idx&63;
        const float* o=mori+(size_t)b*CMNT*NCELL+idx;
        int ai=0; float bv=o[0];
        for(int ch=1;ch<CMNT;ch++){ float v=o[(size_t)ch*NCELL]; if(v>bv){bv=v;ai=ch;} }
        const float* xo=mxo+(size_t)b*COFF*NCELL+idx;
        int xi=0; float bx=xo[0];
        for(int ch=1;ch<COFF;ch++){ float v=xo[(size_t)ch*NCELL]; if(v>bx){bx=v;xi=ch;} }
        const float* yo=myo+(size_t)b*COFF*NCELL+idx;
        int yi=0; float by=yo[0];
        for(int ch=1;ch<COFF;ch++){ float v=yo[(size_t)ch*NCELL]; if(v>by){by=v;yi=ch;} }
        ang=((float)ai*2.0f-89.0f)*0.017453292519943295f;
        xc=(float)c*8.0f+(float)xi;
        yc=(float)r*8.0f+(float)yi;
    }
    if(tid==0) s_nv=0;
    __syncthreads();
    sx[tid]=xc; sy[tid]=yc; sa[tid]=ang; skeep[tid]=valid?1:0;
    atomicMax(&s_nv, valid?(tid+1):0);
    __syncthreads();
    int nv=s_nv;
    for(int i=0;i<nv;i++){
        if(skeep[i] && tid>i && skeep[tid]){
            float dx=sx[tid]-sx[i], dy=sy[tid]-sy[i];
            float d=sqrtf(dx*dx+dy*dy);
            float da=fabsf(sa[tid]-sa[i]);
            da=fminf(da, 6.2831853071795864f-da);
            if(d<16.0f && da<0.52359877559829887f) skeep[tid]=0;
        }
        __syncthreads();
    }
    float kf = skeep[tid]?1.0f:0.0f;
    float* om=out + MINUT_OFF + (size_t)b*KCAND*4 + (size_t)tid*4;
    om[0]=kf*xc; om[1]=kf*yc; om[2]=kf*ang; om[3]=kf*score;
    out[KEEP_OFF + (size_t)b*KCAND + tid]=kf;
}

// -------- finalize: enh_vis, mask*255, ori_field (mask-predicated argmax) --------
__global__ void finalize(const float* __restrict__ enh, const float* __restrict__ oriup,
                         float* __restrict__ out){
    int i=blockIdx.x*blockDim.x+threadIdx.x;
    if(i>=BNUM*NPIX) return;
    int b=i/NPIX, p=i%NPIX;
    float m=g_maskup[i];
    out[MASK_OFF+i]=m*255.0f;
    float emin=ord2f(g_emin[b]);
    float emax=ord2f(g_emax[b]);
    float e=enh[i]*m;
    out[ENH_OFF+i]=(e-emin)/(emax-emin+1e-8f)*255.0f;
    float of=0.0f;
    if(m!=0.0f){
        const float* o=oriup+(size_t)b*CORI*NPIX+p;
        int ai=0; float bv=o[0];
        for(int ch=1;ch<CORI;ch++){ float v=o[(size_t)ch*NPIX]; if(v>bv){bv=v;ai=ch;} }
        of=((float)ai*2.0f-90.0f)*0.017453292519943295f*m;
    }
    out[ORI_OFF+i]=of;
}

extern "C" void kernel_launch(void* const* d_in, const int* in_sizes, int n_in,
                              void* d_out, int out_size){
    const float* seg    =(const float*)d_in[0];
    const float* segup  =(const float*)d_in[1];
    const float* oriup  =(const float*)d_in[2];
    const float* enh    =(const float*)d_in[3];
    const float* mscore =(const float*)d_in[4];
    const float* mori   =(const float*)d_in[5];
    const float* mxo    =(const float*)d_in[6];
    const float* myo    =(const float*)d_in[7];
    float* out=(float*)d_out;

    int nSmall=(BNUM*NCELL+255)/256;
    int nBig  =(BNUM*NPIX +255)/256;
    int nVec  =(BNUM*NPIX/4+255)/256;   // 1024 blocks

    small_erode<<<nSmall,256>>>(seg);    // includes minmax init
    small_dilate<<<nSmall,256>>>();

    up_v4<true ,true ><<<nVec,256>>>(segup, g_tA);   // vmin + rint
    up_h4<true ><<<nVec,256>>>(g_tA, g_tB);          // hmin
    up_v4<false,false><<<nVec,256>>>(g_tB, g_tA);    // vmax
    up_h4<false><<<nVec,256>>>(g_tA, g_maskup);      // hmax

    {
        dim3 g(64,BNUM);
        enh_minmax<<<g,256>>>(enh);
    }

    detect_nms<<<BNUM,1024>>>(mscore, mori, mxo, myo, out);
    finalize<<<nBig,256>>>(enh, oriup, out);
}